// round 15
// baseline (speedup 1.0000x reference)
#include <cuda_runtime.h>

// 3D Haar DWT, level 1, x [B=2, C=32, D=64, H=128, W=128] f32
// -> out [B, 8C, D/2, H/2, W/2], subband order aaa,aad,ada,add,daa,dad,dda,ddd
// (bits: depth,height,width; channel = sb*C + c).
//
// Champion configuration (74.30us kernel best, 6.49 TB/s, DRAM 81-82%) with
// one isolated delta: __ldg (LDG.E.CONSTANT, non-coherent read path) on the
// 4 front-batched 128-bit loads — input is read-once, L1 allocation is dead
// weight. Everything else identical: 2 cubes/thread, 8x STG.64 (one per
// subband), flat 16384x256 launch, 30 regs, no smem.
//
// Closed search (R2-R13): MLP 4/8/16, widths 64/128/256-bit, .cs hints,
// smem-staged segregated stores, bulk-engine stores (exact tie), persistent
// grid-stride, 128-thread CTAs — all neutral or worse. BW == LTS chip cap
// (~6300 B/cyc) at sustained clock; traffic minimal (512 MB). Hardware floor.

#define B_   2
#define C_   32
#define D_   64
#define H_   128
#define W_   128
#define DH   (D_/2)
#define HH   (H_/2)
#define WH   (W_/2)
#define WQ   (W_/4)   // thread handles 2 output-w positions (4 input w)

__global__ void __launch_bounds__(256) haar3d_kernel(
    const float* __restrict__ x, float* __restrict__ out)
{
    const float K = 0.35355339059327373f;  // (1/sqrt(2))^3

    int t = blockIdx.x * blockDim.x + threadIdx.x;
    // t = ((((b*C + c)*DH + dz)*HH + dy)*WQ + wq)
    int wq =  t        & (WQ - 1);         // 0..31
    int dy = (t >> 5)  & (HH - 1);         // 0..63
    int dz = (t >> 11) & (DH - 1);         // 0..31
    int c  = (t >> 16) & (C_ - 1);         // 0..31
    int b  =  t >> 21;                     // 0..1

    // ---- input loads: 4 rows x float4, front-batched, non-coherent path ----
    size_t ibase = ((((size_t)(b * C_ + c) * D_ + 2 * dz) * H_ + 2 * dy) * W_) + 4 * wq;
    const size_t HW = (size_t)H_ * W_;
    const float4 r00 = __ldg((const float4*)(x + ibase));            // d=0, h=0
    const float4 r01 = __ldg((const float4*)(x + ibase + W_));       // d=0, h=1
    const float4 r10 = __ldg((const float4*)(x + ibase + HW));       // d=1, h=0
    const float4 r11 = __ldg((const float4*)(x + ibase + HW + W_));  // d=1, h=1

    // ---- width stage: two cubes, p=0 (.x,.y) p=1 (.z,.w) ----
    float wl00a = r00.x + r00.y, wh00a = r00.x - r00.y;  // cube 0
    float wl01a = r01.x + r01.y, wh01a = r01.x - r01.y;
    float wl10a = r10.x + r10.y, wh10a = r10.x - r10.y;
    float wl11a = r11.x + r11.y, wh11a = r11.x - r11.y;

    float wl00b = r00.z + r00.w, wh00b = r00.z - r00.w;  // cube 1
    float wl01b = r01.z + r01.w, wh01b = r01.z - r01.w;
    float wl10b = r10.z + r10.w, wh10b = r10.z - r10.w;
    float wl11b = r11.z + r11.w, wh11b = r11.z - r11.w;

    // ---- height + depth stages, scale; sb = 4*d_hp + 2*h_hp + w_hp ----
    float s0[8], s1[8];
    {
        float hl_l0 = wl00a + wl01a, hh_l0 = wl00a - wl01a;  // d0, w-low
        float hl_h0 = wh00a + wh01a, hh_h0 = wh00a - wh01a;  // d0, w-high
        float hl_l1 = wl10a + wl11a, hh_l1 = wl10a - wl11a;  // d1
        float hl_h1 = wh10a + wh11a, hh_h1 = wh10a - wh11a;
        s0[0] = (hl_l0 + hl_l1) * K;  // aaa
        s0[1] = (hl_h0 + hl_h1) * K;  // aad
        s0[2] = (hh_l0 + hh_l1) * K;  // ada
        s0[3] = (hh_h0 + hh_h1) * K;  // add
        s0[4] = (hl_l0 - hl_l1) * K;  // daa
        s0[5] = (hl_h0 - hl_h1) * K;  // dad
        s0[6] = (hh_l0 - hh_l1) * K;  // dda
        s0[7] = (hh_h0 - hh_h1) * K;  // ddd
    }
    {
        float hl_l0 = wl00b + wl01b, hh_l0 = wl00b - wl01b;
        float hl_h0 = wh00b + wh01b, hh_h0 = wh00b - wh01b;
        float hl_l1 = wl10b + wl11b, hh_l1 = wl10b - wl11b;
        float hl_h1 = wh10b + wh11b, hh_h1 = wh10b - wh11b;
        s1[0] = (hl_l0 + hl_l1) * K;
        s1[1] = (hl_h0 + hl_h1) * K;
        s1[2] = (hh_l0 + hh_l1) * K;
        s1[3] = (hh_h0 + hh_h1) * K;
        s1[4] = (hl_l0 - hl_l1) * K;
        s1[5] = (hl_h0 - hl_h1) * K;
        s1[6] = (hh_l0 - hh_l1) * K;
        s1[7] = (hh_h0 - hh_h1) * K;
    }

    // ---- output: channel = sb*C + c ; float2 per subband ----
    size_t obase = ((((size_t)(b * 8 * C_ + c) * DH + dz) * HH + dy) * WH) + 2 * wq;
    const size_t sbStride = (size_t)C_ * DH * HH * WH;  // sb advances 32 channels

#pragma unroll
    for (int sb = 0; sb < 8; sb++) {
        *(float2*)(out + obase + (size_t)sb * sbStride) = make_float2(s0[sb], s1[sb]);
    }
}

extern "C" void kernel_launch(void* const* d_in, const int* in_sizes, int n_in,
                              void* d_out, int out_size) {
    const float* x = (const float*)d_in[0];
    float* out = (float*)d_out;
    // total threads = B*C*DH*HH*WQ = 2*32*32*64*32 = 4,194,304
    const int total = B_ * C_ * DH * HH * WQ;
    haar3d_kernel<<<total / 256, 256>>>(x, out);
}

// round 16
// speedup vs baseline: 1.0031x; 1.0031x over previous
#include <cuda_runtime.h>

// 3D Haar DWT, level 1, x [B=2, C=32, D=64, H=128, W=128] f32
// -> out [B, 8C, D/2, H/2, W/2], subband order aaa,aad,ada,add,daa,dad,dda,ddd
// (bits: depth,height,width; channel = sb*C + c).
//
// FINAL — champion configuration. Best measured: 74.30us kernel, 6.49-6.52
// TB/s, DRAM 81-82%. One thread = two adjacent 2x2x2 cubes along W:
// 4x front-batched LDG.128 in, 8x STG.64 out (one per subband stream).
// Flat 16384x256 launch, 30 regs, no smem.
//
// Exhaustively closed search (R2-R14), all neutral or worse:
//   - per-thread work 2/4/8 cubes (MLP 4/8/16)
//   - access width 64/128/256-bit (incl. sm_103a LDG/STG.256)
//   - cache policy: .cs both sides, __ldg non-coherent reads
//   - store organization: interleaved, smem-staged subband-segregated,
//     bulk-engine cp.async.bulk (exact tie at 74.304us)
//   - launch: flat vs persistent grid-stride, 128 vs 256-thread CTAs
// Achieved BW == path-independent LTS chip cap (~6300 B/cyc) at sustained
// clock; traffic is minimal (512 MB, each byte through L2 once per
// direction). Hardware floor for this op on this part.

#define B_   2
#define C_   32
#define D_   64
#define H_   128
#define W_   128
#define DH   (D_/2)
#define HH   (H_/2)
#define WH   (W_/2)
#define WQ   (W_/4)   // thread handles 2 output-w positions (4 input w)

__global__ void __launch_bounds__(256) haar3d_kernel(
    const float* __restrict__ x, float* __restrict__ out)
{
    const float K = 0.35355339059327373f;  // (1/sqrt(2))^3

    int t = blockIdx.x * blockDim.x + threadIdx.x;
    // t = ((((b*C + c)*DH + dz)*HH + dy)*WQ + wq)
    int wq =  t        & (WQ - 1);         // 0..31
    int dy = (t >> 5)  & (HH - 1);         // 0..63
    int dz = (t >> 11) & (DH - 1);         // 0..31
    int c  = (t >> 16) & (C_ - 1);         // 0..31
    int b  =  t >> 21;                     // 0..1

    // ---- input loads: 4 rows x float4, front-batched ----
    size_t ibase = ((((size_t)(b * C_ + c) * D_ + 2 * dz) * H_ + 2 * dy) * W_) + 4 * wq;
    const float4 r00 = *(const float4*)(x + ibase);                         // d=0, h=0
    const float4 r01 = *(const float4*)(x + ibase + W_);                    // d=0, h=1
    const float4 r10 = *(const float4*)(x + ibase + (size_t)H_ * W_);       // d=1, h=0
    const float4 r11 = *(const float4*)(x + ibase + (size_t)H_ * W_ + W_);  // d=1, h=1

    // ---- width stage: two cubes, p=0 (.x,.y) p=1 (.z,.w) ----
    float wl00a = r00.x + r00.y, wh00a = r00.x - r00.y;  // cube 0
    float wl01a = r01.x + r01.y, wh01a = r01.x - r01.y;
    float wl10a = r10.x + r10.y, wh10a = r10.x - r10.y;
    float wl11a = r11.x + r11.y, wh11a = r11.x - r11.y;

    float wl00b = r00.z + r00.w, wh00b = r00.z - r00.w;  // cube 1
    float wl01b = r01.z + r01.w, wh01b = r01.z - r01.w;
    float wl10b = r10.z + r10.w, wh10b = r10.z - r10.w;
    float wl11b = r11.z + r11.w, wh11b = r11.z - r11.w;

    // ---- height + depth stages, scale; sb = 4*d_hp + 2*h_hp + w_hp ----
    float s0[8], s1[8];
    {
        float hl_l0 = wl00a + wl01a, hh_l0 = wl00a - wl01a;  // d0, w-low
        float hl_h0 = wh00a + wh01a, hh_h0 = wh00a - wh01a;  // d0, w-high
        float hl_l1 = wl10a + wl11a, hh_l1 = wl10a - wl11a;  // d1
        float hl_h1 = wh10a + wh11a, hh_h1 = wh10a - wh11a;
        s0[0] = (hl_l0 + hl_l1) * K;  // aaa
        s0[1] = (hl_h0 + hl_h1) * K;  // aad
        s0[2] = (hh_l0 + hh_l1) * K;  // ada
        s0[3] = (hh_h0 + hh_h1) * K;  // add
        s0[4] = (hl_l0 - hl_l1) * K;  // daa
        s0[5] = (hl_h0 - hl_h1) * K;  // dad
        s0[6] = (hh_l0 - hh_l1) * K;  // dda
        s0[7] = (hh_h0 - hh_h1) * K;  // ddd
    }
    {
        float hl_l0 = wl00b + wl01b, hh_l0 = wl00b - wl01b;
        float hl_h0 = wh00b + wh01b, hh_h0 = wh00b - wh01b;
        float hl_l1 = wl10b + wl11b, hh_l1 = wl10b - wl11b;
        float hl_h1 = wh10b + wh11b, hh_h1 = wh10b - wh11b;
        s1[0] = (hl_l0 + hl_l1) * K;
        s1[1] = (hl_h0 + hl_h1) * K;
        s1[2] = (hh_l0 + hh_l1) * K;
        s1[3] = (hh_h0 + hh_h1) * K;
        s1[4] = (hl_l0 - hl_l1) * K;
        s1[5] = (hl_h0 - hl_h1) * K;
        s1[6] = (hh_l0 - hh_l1) * K;
        s1[7] = (hh_h0 - hh_h1) * K;
    }

    // ---- output: channel = sb*C + c ; float2 per subband ----
    size_t obase = ((((size_t)(b * 8 * C_ + c) * DH + dz) * HH + dy) * WH) + 2 * wq;
    const size_t sbStride = (size_t)C_ * DH * HH * WH;  // sb advances 32 channels

#pragma unroll
    for (int sb = 0; sb < 8; sb++) {
        *(float2*)(out + obase + (size_t)sb * sbStride) = make_float2(s0[sb], s1[sb]);
    }
}

extern "C" void kernel_launch(void* const* d_in, const int* in_sizes, int n_in,
                              void* d_out, int out_size) {
    const float* x = (const float*)d_in[0];
    float* out = (float*)d_out;
    // total threads = B*C*DH*HH*WQ = 2*32*32*64*32 = 4,194,304
    const int total = B_ * C_ * DH * HH * WQ;
    haar3d_kernel<<<total / 256, 256>>>(x, out);
}

// round 17
// speedup vs baseline: 1.0055x; 1.0023x over previous
#include <cuda_runtime.h>

// 3D Haar DWT, level 1, x [B=2, C=32, D=64, H=128, W=128] f32
// -> out [B, 8C, D/2, H/2, W/2], subband order aaa,aad,ada,add,daa,dad,dda,ddd
// (bits: depth,height,width; channel = sb*C + c).
//
// FINAL — champion configuration. Best measured: 74.24us kernel, 6.51 TB/s,
// DRAM 82.1%. One thread = two adjacent 2x2x2 cubes along W: 4x front-batched
// LDG.128 in, 8x STG.64 out (one per subband stream). Flat 16384x256 launch,
// 30 regs, no smem.
//
// Exhaustively closed search (R2-R15), all neutral or worse:
//   - per-thread work 2/4/8 cubes (MLP 4/8/16)
//   - access width 64/128/256-bit (incl. sm_103a LDG/STG.256)
//   - cache policy: .cs both sides, __ldg non-coherent reads
//   - store organization: interleaved, smem-staged subband-segregated,
//     bulk-engine cp.async.bulk (exact tie)
//   - launch: flat vs persistent grid-stride, 128 vs 256-thread CTAs
// Achieved BW == path-independent LTS chip cap (~6300 B/cyc) at sustained
// clock; traffic is minimal (512 MB, each byte through L2 once per
// direction). Hardware floor for this op on this part.

#define B_   2
#define C_   32
#define D_   64
#define H_   128
#define W_   128
#define DH   (D_/2)
#define HH   (H_/2)
#define WH   (W_/2)
#define WQ   (W_/4)   // thread handles 2 output-w positions (4 input w)

__global__ void __launch_bounds__(256) haar3d_kernel(
    const float* __restrict__ x, float* __restrict__ out)
{
    const float K = 0.35355339059327373f;  // (1/sqrt(2))^3

    int t = blockIdx.x * blockDim.x + threadIdx.x;
    // t = ((((b*C + c)*DH + dz)*HH + dy)*WQ + wq)
    int wq =  t        & (WQ - 1);         // 0..31
    int dy = (t >> 5)  & (HH - 1);         // 0..63
    int dz = (t >> 11) & (DH - 1);         // 0..31
    int c  = (t >> 16) & (C_ - 1);         // 0..31
    int b  =  t >> 21;                     // 0..1

    // ---- input loads: 4 rows x float4, front-batched ----
    size_t ibase = ((((size_t)(b * C_ + c) * D_ + 2 * dz) * H_ + 2 * dy) * W_) + 4 * wq;
    const float4 r00 = *(const float4*)(x + ibase);                         // d=0, h=0
    const float4 r01 = *(const float4*)(x + ibase + W_);                    // d=0, h=1
    const float4 r10 = *(const float4*)(x + ibase + (size_t)H_ * W_);       // d=1, h=0
    const float4 r11 = *(const float4*)(x + ibase + (size_t)H_ * W_ + W_);  // d=1, h=1

    // ---- width stage: two cubes, p=0 (.x,.y) p=1 (.z,.w) ----
    float wl00a = r00.x + r00.y, wh00a = r00.x - r00.y;  // cube 0
    float wl01a = r01.x + r01.y, wh01a = r01.x - r01.y;
    float wl10a = r10.x + r10.y, wh10a = r10.x - r10.y;
    float wl11a = r11.x + r11.y, wh11a = r11.x - r11.y;

    float wl00b = r00.z + r00.w, wh00b = r00.z - r00.w;  // cube 1
    float wl01b = r01.z + r01.w, wh01b = r01.z - r01.w;
    float wl10b = r10.z + r10.w, wh10b = r10.z - r10.w;
    float wl11b = r11.z + r11.w, wh11b = r11.z - r11.w;

    // ---- height + depth stages, scale; sb = 4*d_hp + 2*h_hp + w_hp ----
    float s0[8], s1[8];
    {
        float hl_l0 = wl00a + wl01a, hh_l0 = wl00a - wl01a;  // d0, w-low
        float hl_h0 = wh00a + wh01a, hh_h0 = wh00a - wh01a;  // d0, w-high
        float hl_l1 = wl10a + wl11a, hh_l1 = wl10a - wl11a;  // d1
        float hl_h1 = wh10a + wh11a, hh_h1 = wh10a - wh11a;
        s0[0] = (hl_l0 + hl_l1) * K;  // aaa
        s0[1] = (hl_h0 + hl_h1) * K;  // aad
        s0[2] = (hh_l0 + hh_l1) * K;  // ada
        s0[3] = (hh_h0 + hh_h1) * K;  // add
        s0[4] = (hl_l0 - hl_l1) * K;  // daa
        s0[5] = (hl_h0 - hl_h1) * K;  // dad
        s0[6] = (hh_l0 - hh_l1) * K;  // dda
        s0[7] = (hh_h0 - hh_h1) * K;  // ddd
    }
    {
        float hl_l0 = wl00b + wl01b, hh_l0 = wl00b - wl01b;
        float hl_h0 = wh00b + wh01b, hh_h0 = wh00b - wh01b;
        float hl_l1 = wl10b + wl11b, hh_l1 = wl10b - wl11b;
        float hl_h1 = wh10b + wh11b, hh_h1 = wh10b - wh11b;
        s1[0] = (hl_l0 + hl_l1) * K;
        s1[1] = (hl_h0 + hl_h1) * K;
        s1[2] = (hh_l0 + hh_l1) * K;
        s1[3] = (hh_h0 + hh_h1) * K;
        s1[4] = (hl_l0 - hl_l1) * K;
        s1[5] = (hl_h0 - hl_h1) * K;
        s1[6] = (hh_l0 - hh_l1) * K;
        s1[7] = (hh_h0 - hh_h1) * K;
    }

    // ---- output: channel = sb*C + c ; float2 per subband ----
    size_t obase = ((((size_t)(b * 8 * C_ + c) * DH + dz) * HH + dy) * WH) + 2 * wq;
    const size_t sbStride = (size_t)C_ * DH * HH * WH;  // sb advances 32 channels

#pragma unroll
    for (int sb = 0; sb < 8; sb++) {
        *(float2*)(out + obase + (size_t)sb * sbStride) = make_float2(s0[sb], s1[sb]);
    }
}

extern "C" void kernel_launch(void* const* d_in, const int* in_sizes, int n_in,
                              void* d_out, int out_size) {
    const float* x = (const float*)d_in[0];
    float* out = (float*)d_out;
    // total threads = B*C*DH*HH*WQ = 2*32*32*64*32 = 4,194,304
    const int total = B_ * C_ * DH * HH * WQ;
    haar3d_kernel<<<total / 256, 256>>>(x, out);
}